// round 1
// baseline (speedup 1.0000x reference)
#include <cuda_runtime.h>

// Problem constants (fixed by the reference: N=8192, K=10, M=3)
#define N_ROWS 8192
#define K_DIM  10
#define M_DIM  3

// Scratch for the (8192 x 3) intermediate — device global (no allocs allowed).
__device__ float g_mid[N_ROWS * M_DIM];

// ---------------------------------------------------------------------------
// Stage 1: mid[n][m] = max_k( |x[n][k]| + |w1[m][k]| )
// One thread per row n. w1 (30 floats) staged in shared.
// ---------------------------------------------------------------------------
__global__ void stage1_kernel(const float* __restrict__ x,
                              const float* __restrict__ w1) {
    __shared__ float sw[M_DIM * K_DIM];
    int tid = threadIdx.x;
    if (tid < M_DIM * K_DIM) sw[tid] = fabsf(w1[tid]);
    __syncthreads();

    int n = blockIdx.x * blockDim.x + tid;
    if (n >= N_ROWS) return;

    float xa[K_DIM];
#pragma unroll
    for (int k = 0; k < K_DIM; ++k) xa[k] = fabsf(x[n * K_DIM + k]);

#pragma unroll
    for (int m = 0; m < M_DIM; ++m) {
        float v = xa[0] + sw[m * K_DIM + 0];
#pragma unroll
        for (int k = 1; k < K_DIM; ++k)
            v = fmaxf(v, xa[k] + sw[m * K_DIM + k]);
        g_mid[n * M_DIM + m] = v;
    }
}

// ---------------------------------------------------------------------------
// Stage 2: out[i][j] = max_{m<3}( mid[i][m] + mid[j][m] )
// Block tile: 32 rows (i) x 1024 cols (j). 256 threads; each thread owns
// 4 consecutive j (one float4 store per row), loops over the 32 rows.
// mid values for the tile staged in shared once.
// ---------------------------------------------------------------------------
#define TILE_I 32
#define TILE_J 1024
#define THREADS 256

__global__ __launch_bounds__(THREADS)
void stage2_kernel(float* __restrict__ out) {
    __shared__ float sb[TILE_J * M_DIM];  // 12 KB: mid for j-tile
    __shared__ float sa[TILE_I * M_DIM];  // mid for i-tile

    const int j0 = blockIdx.x * TILE_J;
    const int i0 = blockIdx.y * TILE_I;
    const int tid = threadIdx.x;

    // cooperative stage of mid tiles (coalesced: contiguous in g_mid)
    for (int idx = tid; idx < TILE_J * M_DIM; idx += THREADS)
        sb[idx] = g_mid[j0 * M_DIM + idx];
    for (int idx = tid; idx < TILE_I * M_DIM; idx += THREADS)
        sa[idx] = g_mid[i0 * M_DIM + idx];
    __syncthreads();

    // Each thread: 4 consecutive j values -> 12 b-components in registers.
    const int jl = tid * 4;  // local j within tile
    float b0x = sb[(jl + 0) * M_DIM + 0], b0y = sb[(jl + 0) * M_DIM + 1], b0z = sb[(jl + 0) * M_DIM + 2];
    float b1x = sb[(jl + 1) * M_DIM + 0], b1y = sb[(jl + 1) * M_DIM + 1], b1z = sb[(jl + 1) * M_DIM + 2];
    float b2x = sb[(jl + 2) * M_DIM + 0], b2y = sb[(jl + 2) * M_DIM + 1], b2z = sb[(jl + 2) * M_DIM + 2];
    float b3x = sb[(jl + 3) * M_DIM + 0], b3y = sb[(jl + 3) * M_DIM + 1], b3z = sb[(jl + 3) * M_DIM + 2];

    float4* out4 = reinterpret_cast<float4*>(out + (long)i0 * N_ROWS + j0 + jl);
    const long row_stride4 = N_ROWS / 4;  // in float4 units

#pragma unroll 4
    for (int r = 0; r < TILE_I; ++r) {
        const float a0 = sa[r * M_DIM + 0];
        const float a1 = sa[r * M_DIM + 1];
        const float a2 = sa[r * M_DIM + 2];

        float4 v;
        v.x = fmaxf(fmaxf(a0 + b0x, a1 + b0y), a2 + b0z);
        v.y = fmaxf(fmaxf(a0 + b1x, a1 + b1y), a2 + b1z);
        v.z = fmaxf(fmaxf(a0 + b2x, a1 + b2y), a2 + b2z);
        v.w = fmaxf(fmaxf(a0 + b3x, a1 + b3y), a2 + b3z);

        out4[(long)r * row_stride4] = v;
    }
}

// ---------------------------------------------------------------------------
extern "C" void kernel_launch(void* const* d_in, const int* in_sizes, int n_in,
                              void* d_out, int out_size) {
    const float* x  = (const float*)d_in[0];   // (8192, 10)
    const float* w1 = (const float*)d_in[1];   // (3, 10)
    float* out = (float*)d_out;                // (8192, 8192)

    stage1_kernel<<<N_ROWS / 256, 256>>>(x, w1);

    dim3 grid(N_ROWS / TILE_J, N_ROWS / TILE_I);  // (8, 256) = 2048 blocks
    stage2_kernel<<<grid, THREADS>>>(out);
}